// round 13
// baseline (speedup 1.0000x reference)
#include <cuda_runtime.h>
#include <cuda_fp16.h>

// ---------------- problem constants ----------------
#define N_NODES 10000
#define N_RELS  50
#define R_AUG   101                    // 2*N_RELS + 1
#define D       128
#define N_EDGES 320000
#define E_AUG   (2*N_EDGES + N_NODES)  // 650000
#define N_SEG   (R_AUG * N_NODES)      // 1010000
#define N_BATCH 65536

// persistent layer config: 1 CTA/SM, warp-specialized, M-tile 64
#define TM      64
#define NTILES  ((N_NODES + TM - 1) / TM)          // 157
#define NITEMS  (NTILES * R_AUG)                   // 15857
#define NCTA    148
#define WPC     ((NITEMS + NCTA - 1) / NCTA)       // 108
#define NSLAB   2
#define SEG_CHUNK ((N_SEG + NCTA - 1) / NCTA)      // 6825

// fp16 tile row stride: 128 + 8 pad = 136 halves = 272 bytes
#define TS      272
#define APLANE  (64 * TS)                           // 17408
#define BPLANE  (128 * TS)                          // 34816

// smem layout (bytes): A double-buffered (hi|lo per buf), B double-buffered
#define ABUF(i)  ((i) * 2 * APLANE)                 // hi at +0, lo at +APLANE
#define BBUF(i)  (4 * APLANE + (i) * BPLANE)
#define SMEM_TOT (4 * APLANE + 2 * BPLANE + 64)     // 139,328 (~136.1 KB) -> 1/SM

typedef unsigned long long u64;
typedef unsigned int u32;
typedef unsigned short u16;

// ---------------- static device scratch ----------------
__device__ int   g_deg[N_SEG];
__device__ int   g_rowptr[N_SEG + 1];
__device__ int   g_cursor[N_SEG];
__device__ int   g_ctasum[NCTA];
__device__ int   g_csr[E_AUG];                         // src only
__device__ u16   g_Bt1[(size_t)R_AUG * 16384];         // layer1 W fp16, row=n col=k
__device__ u16   g_Bt2[(size_t)R_AUG * 16384];         // layer2 W
__device__ float g_h1[N_NODES * D];
__device__ float g_h2[N_NODES * D];
__device__ float g_partial[(size_t)NSLAB * N_NODES * D];
__device__ unsigned g_bcnt[8];                         // grid barrier counters (self-reset)
__device__ unsigned g_brel[8];                         // grid barrier release epochs (monotonic)

// ---------------- small helpers ----------------
__device__ __forceinline__ u32 smem_u32(const void* p) {
    u32 a;
    asm("{ .reg .u64 t; cvta.to.shared.u64 t, %1; cvt.u32.u64 %0, t; }" : "=r"(a) : "l"(p));
    return a;
}
__device__ __forceinline__ u16 f2h(float v) {
    u16 r; asm("cvt.rn.f16.f32 %0, %1;" : "=h"(r) : "f"(v)); return r;
}
__device__ __forceinline__ float h2f(u16 v) {
    float r; asm("cvt.f32.f16 %0, %1;" : "=f"(r) : "h"(v)); return r;
}

#define LDSM4(r, addr)                                                          \
    asm volatile("ldmatrix.sync.aligned.m8n8.x4.shared.b16 {%0,%1,%2,%3}, [%4];"\
        : "=r"((r)[0]), "=r"((r)[1]), "=r"((r)[2]), "=r"((r)[3]) : "r"(addr))

#define MMA16816(c, a, b0_, b1_)                                                \
    asm volatile("mma.sync.aligned.m16n8k16.row.col.f32.f16.f16.f32 "           \
        "{%0,%1,%2,%3}, {%4,%5,%6,%7}, {%8,%9}, {%0,%1,%2,%3};"                 \
        : "+f"((c)[0]), "+f"((c)[1]), "+f"((c)[2]), "+f"((c)[3])                \
        : "r"((a)[0]), "r"((a)[1]), "r"((a)[2]), "r"((a)[3]), "r"(b0_), "r"(b1_))

#define CP_ASYNC16(dst, src)                                                    \
    asm volatile("cp.async.cg.shared.global [%0], [%1], 16;" :: "r"(dst), "l"(src))
#define CP_COMMIT() asm volatile("cp.async.commit_group;" ::: "memory")
#define CP_WAIT0()  asm volatile("cp.async.wait_group 0;" ::: "memory")

// ---- replay-safe software grid barrier (all NCTA CTAs co-resident: 1/SM) ----
__device__ __forceinline__ void grid_bar(int slot) {
    __threadfence();
    __syncthreads();
    if (threadIdx.x == 0) {
        volatile unsigned* rel = (volatile unsigned*)&g_brel[slot];
        unsigned e0 = *rel;
        unsigned t = atomicAdd(&g_bcnt[slot], 1u);
        if (t == NCTA - 1) {
            g_bcnt[slot] = 0;
            __threadfence();
            atomicAdd(&g_brel[slot], 1u);
        } else {
            while (*rel == e0) { }
        }
        __threadfence();
    }
    __syncthreads();
}

// ---- block exclusive scan over 256 ints; returns exclusive, sets total ----
__device__ __forceinline__ int block_excl_scan(int v, int* ssc, int& total) {
    int lane = threadIdx.x & 31, w = threadIdx.x >> 5;
    int x = v;
    #pragma unroll
    for (int o = 1; o < 32; o <<= 1) {
        int y = __shfl_up_sync(0xffffffffu, x, o);
        if (lane >= o) x += y;
    }
    if (lane == 31) ssc[w] = x;
    __syncthreads();
    if (w == 0) {
        int tval = (lane < 8) ? ssc[lane] : 0;
        #pragma unroll
        for (int o = 1; o < 8; o <<= 1) {
            int y = __shfl_up_sync(0xffffffffu, tval, o);
            if (lane >= o) tval += y;
        }
        if (lane < 8) ssc[lane] = tval;    // inclusive warp totals
    }
    __syncthreads();
    int wbase = (w > 0) ? ssc[w - 1] : 0;
    total = ssc[7];
    __syncthreads();
    return wbase + x - v;
}

__device__ __forceinline__ void aug_edge(const int* __restrict__ g, int e,
                                         int& seg, int& src) {
    if (e < N_EDGES) {
        int s = g[e*3+0], p = g[e*3+1], o = g[e*3+2];
        seg = p * N_NODES + o;  src = s;
    } else if (e < 2*N_EDGES) {
        int e2 = e - N_EDGES;
        int s = g[e2*3+0], p = g[e2*3+1], o = g[e2*3+2];
        seg = (p + N_RELS) * N_NODES + s;  src = o;
    } else {
        int i = e - 2*N_EDGES;
        seg = 2*N_RELS*N_NODES + i;  src = i;
    }
}

// ---------------- W -> fp16 B^T plane (row=n, col=k) ----------------
__global__ void convert_w_kernel(const float* __restrict__ W, u16* __restrict__ Bt) {
    int r = blockIdx.x;
    const float* Wr = W + (size_t)r * (D * D);
    u16* B = Bt + (size_t)r * 16384;
    for (int idx = threadIdx.x; idx < D * D; idx += blockDim.x) {
        int k = idx >> 7, n = idx & 127;
        B[n * D + k] = f2h(Wr[k * D + n]);
    }
}

__global__ void zero_partial_kernel() {
    int i = blockIdx.x * blockDim.x + threadIdx.x;
    const int n4 = NSLAB * N_NODES * D / 4;
    if (i < n4) ((float4*)g_partial)[i] = make_float4(0.f, 0.f, 0.f, 0.f);
}

// ---------------- flush consumer accumulators to a partial slab ----------------
// consumer warp tile: 32x64 (wm = warp&1 -> m offset, wn = warp>>1 -> n offset)
__device__ __forceinline__ void flush_acc(float acc[2][8][4], int cur_t,
                                          int wm, int wn, int lane) {
    int slab_i = blockIdx.x - (cur_t * R_AUG) / WPC;
    float* slab = g_partial + (size_t)slab_i * (N_NODES * D);
    int r0 = cur_t * TM + wm * 32 + (lane >> 2);
    int cb = wn * 64 + (lane & 3) * 2;
    #pragma unroll
    for (int mf = 0; mf < 2; mf++) {
        int rowA = r0 + mf * 16;
        int rowB = rowA + 8;
        #pragma unroll
        for (int nf = 0; nf < 8; nf++) {
            int col = cb + nf * 8;
            if (rowA < N_NODES)
                *(float2*)(slab + (size_t)rowA * D + col) =
                    make_float2(acc[mf][nf][0], acc[mf][nf][1]);
            if (rowB < N_NODES)
                *(float2*)(slab + (size_t)rowB * D + col) =
                    make_float2(acc[mf][nf][2], acc[mf][nf][3]);
        }
    }
}

// ---- producers (128 threads, ptid 0..127): cp.async B tile into buffer ----
__device__ __forceinline__ void prefetch_B(u32 smbuf, const u16* __restrict__ Bt,
                                           int r, int ptid) {
    const char* src_base = (const char*)(Bt + (size_t)r * 16384);
    #pragma unroll
    for (int q = 0; q < 16; q++) {
        int idx = ptid + q * 128;          // 0..2047 16B chunks
        int row = idx >> 4, c16 = idx & 15;
        u32 dst = smbuf + row * TS + c16 * 16;
        const char* src = src_base + row * 256 + c16 * 16;
        CP_ASYNC16(dst, src);
    }
}

// ---- producers: build + convert A hi/lo tiles for one item ----
__device__ __forceinline__ void build_A(char* smem, int abase,
                                        const float* __restrict__ x,
                                        int segbase, int nrows, int ptid) {
    int bsub = ptid & 3;                   // 32-dim chunk
    #pragma unroll
    for (int pass = 0; pass < 2; pass++) {
        int row = (ptid >> 2) + pass * 32;
        float4 a[8];
        #pragma unroll
        for (int q = 0; q < 8; q++) a[q] = make_float4(0.f, 0.f, 0.f, 0.f);
        int deg = 0;
        if (row < nrows) {
            int seg = segbase + row;
            int s = g_rowptr[seg], e = g_rowptr[seg + 1];
            deg = e - s;
            for (int j = s; j < e; ++j) {
                int src = g_csr[j];
                const float4* v = (const float4*)(x + (size_t)src * D + (bsub << 5));
                #pragma unroll
                for (int q = 0; q < 8; q++) {
                    float4 w = v[q];
                    a[q].x += w.x; a[q].y += w.y; a[q].z += w.z; a[q].w += w.w;
                }
            }
        }
        float nrm = 1.0f / fmaxf((float)deg, 1.0f);
        u32* AH = (u32*)(smem + abase + row * TS + (bsub << 6));
        u32* AL = (u32*)(smem + abase + APLANE + row * TS + (bsub << 6));
        #pragma unroll
        for (int q = 0; q < 8; q++) {
            float v0 = a[q].x * nrm, v1 = a[q].y * nrm;
            float v2 = a[q].z * nrm, v3 = a[q].w * nrm;
            u16 h0 = f2h(v0), h1 = f2h(v1), h2 = f2h(v2), h3 = f2h(v3);
            u16 l0 = f2h(v0 - h2f(h0)), l1 = f2h(v1 - h2f(h1));
            u16 l2 = f2h(v2 - h2f(h2)), l3 = f2h(v3 - h2f(h3));
            AH[q*2+0] = (u32)h0 | ((u32)h1 << 16);
            AH[q*2+1] = (u32)h2 | ((u32)h3 << 16);
            AL[q*2+0] = (u32)l0 | ((u32)l1 << 16);
            AL[q*2+1] = (u32)l2 | ((u32)l3 << 16);
        }
    }
}

// ---------------- persistent mega kernel: (optional CSR build) + layer ----------------
extern "C" __global__ void __launch_bounds__(256, 1)
layer_mega_kernel(const float* __restrict__ x, const int* __restrict__ graph,
                  const u16* __restrict__ Bt, int build_csr) {
    extern __shared__ char smem[];
    __shared__ int ssc[16];
    __shared__ int sbase;
    u32 smb = smem_u32(smem);

    int tid  = threadIdx.x;
    int bid  = blockIdx.x;
    int gtid = bid * 256 + tid;
    const int gstride = NCTA * 256;

    // ================= CSR build (layer-1 instance only; all 256 threads) =================
    if (build_csr) {
        for (int i = gtid; i < N_SEG; i += gstride) g_deg[i] = 0;
        grid_bar(0);
        for (int e = gtid; e < E_AUG; e += gstride) {
            int seg, src;
            aug_edge(graph, e, seg, src);
            atomicAdd(&g_deg[seg], 1);
        }
        grid_bar(1);
        int s0 = bid * SEG_CHUNK;
        int s1 = min(s0 + SEG_CHUNK, N_SEG);
        {
            int lsum = 0;
            for (int i = s0 + tid; i < s1; i += 256) lsum += g_deg[i];
            #pragma unroll
            for (int o = 16; o; o >>= 1) lsum += __shfl_xor_sync(0xffffffffu, lsum, o);
            if ((tid & 31) == 0) ssc[tid >> 5] = lsum;
            __syncthreads();
            if (tid < 8) {
                int v = ssc[tid];
                #pragma unroll
                for (int o = 4; o; o >>= 1) v += __shfl_xor_sync(0xffu, v, o);
                if (tid == 0) g_ctasum[bid] = v;
            }
            __syncthreads();
        }
        grid_bar(2);
        {
            int v = (tid < NCTA) ? g_ctasum[tid] : 0;
            int tot;
            int ex = block_excl_scan(v, ssc, tot);
            if (tid == bid) sbase = ex;
            __syncthreads();
            int run = sbase;
            const int nchunk = (SEG_CHUNK + 255) / 256;
            for (int c = 0; c < nchunk; c++) {
                int gi = s0 + c * 256 + tid;
                int dv = (gi < s1) ? g_deg[gi] : 0;
                int ctot;
                int cex = block_excl_scan(dv, ssc, ctot);
                if (gi < s1) {
                    int rp = run + cex;
                    g_rowptr[gi] = rp;
                    g_cursor[gi] = rp;
                }
                run += ctot;
            }
            if (bid == NCTA - 1 && tid == 0) g_rowptr[N_SEG] = E_AUG;
        }
        grid_bar(3);
        for (int e = gtid; e < E_AUG; e += gstride) {
            int seg, src;
            aug_edge(graph, e, seg, src);
            int pos = atomicAdd(&g_cursor[seg], 1);
            g_csr[pos] = src;
        }
        grid_bar(4);
    }

    // ================= warp-specialized layer items =================
    int warp = tid >> 5, lane = tid & 31;
    bool is_consumer = (warp < 4);
    int ptid = tid - 128;                  // producer-local tid (valid when !is_consumer)

    // consumer addressing: warp tile 32x64
    int wm = warp & 1, wn = warp >> 1;     // (only meaningful for consumers)
    u32 rowa = (u32)(wm * 32 + (lane & 15)) * TS + (u32)((lane >> 4) << 3) * 2;
    u32 rowb = (u32)(wn * 64 + ((lane >> 4) << 3) + (lane & 7)) * TS
             + (u32)(((lane >> 3) & 1) << 3) * 2;

    float acc[2][8][4];
    #pragma unroll
    for (int i = 0; i < 2; i++)
        #pragma unroll
        for (int j = 0; j < 8; j++)
            #pragma unroll
            for (int q = 0; q < 4; q++) acc[i][j][q] = 0.f;

    int i0 = bid * WPC;
    int i1 = min(i0 + WPC, NITEMS);
    if (i0 >= i1) return;

    int cur_t = -1;

    // ---- prologue: producers stage item i0 into buffer (i0&1) ----
    if (!is_consumer) {
        int t0 = i0 / R_AUG, r0 = i0 - t0 * R_AUG;
        int tb0 = t0 * TM;
        prefetch_B(smb + BBUF(i0 & 1), Bt, r0, ptid);
        CP_COMMIT();
        build_A(smem, ABUF(i0 & 1), x, r0 * N_NODES + tb0,
                min(TM, N_NODES - tb0), ptid);
        CP_WAIT0();
    }
    __syncthreads();

    for (int it = i0; it < i1; ++it) {
        if (!is_consumer) {
            // ---- producers: stage item it+1 into the other buffer ----
            int nx = it + 1;
            if (nx < i1) {
                int t2 = nx / R_AUG, r2 = nx - t2 * R_AUG;
                int tb2 = t2 * TM;
                prefetch_B(smb + BBUF(nx & 1), Bt, r2, ptid);
                CP_COMMIT();
                build_A(smem, ABUF(nx & 1), x, r2 * N_NODES + tb2,
                        min(TM, N_NODES - tb2), ptid);
                CP_WAIT0();
            }
        } else {
            // ---- consumers: GEMM item it from buffer (it&1) ----
            int t = it / R_AUG;
            if (t != cur_t) {
                if (cur_t >= 0) {
                    flush_acc(acc, cur_t, wm, wn, lane);
                    #pragma unroll
                    for (int i = 0; i < 2; i++)
                        #pragma unroll
                        for (int j = 0; j < 8; j++)
                            #pragma unroll
                            for (int q = 0; q < 4; q++) acc[i][j][q] = 0.f;
                }
                cur_t = t;
            }
            u32 aHb = smb + ABUF(it & 1) + rowa;
            u32 aLb = aHb + APLANE;
            u32 bHb = smb + BBUF(it & 1) + rowb;

            #pragma unroll
            for (int ks = 0; ks < 8; ks++) {
                u32 k2 = (u32)ks * 32;              // k0 * 2 bytes
                u32 aH0[4], aH1[4], aL0[4], aL1[4];
                LDSM4(aH0, aHb + k2);
                LDSM4(aH1, aHb + 16 * TS + k2);
                LDSM4(aL0, aLb + k2);
                LDSM4(aL1, aLb + 16 * TS + k2);
                #pragma unroll
                for (int nh = 0; nh < 4; nh++) {
                    u32 bH[4];
                    LDSM4(bH, bHb + (u32)nh * 16 * TS + k2);
                    int n0 = nh * 2, n1 = nh * 2 + 1;
                    MMA16816(acc[0][n0], aH0, bH[0], bH[1]);
                    MMA16816(acc[0][n0], aL0, bH[0], bH[1]);
                    MMA16816(acc[1][n0], aH1, bH[0], bH[1]);
                    MMA16816(acc[1][n0], aL1, bH[0], bH[1]);
                    MMA16816(acc[0][n1], aH0, bH[2], bH[3]);
                    MMA16816(acc[0][n1], aL0, bH[2], bH[3]);
                    MMA16816(acc[1][n1], aH1, bH[2], bH[3]);
                    MMA16816(acc[1][n1], aL1, bH[2], bH[3]);
                }
            }
        }
        __syncthreads();   // publish buffer (it+1)&1; retire buffer it&1
    }

    if (is_consumer && cur_t >= 0) flush_acc(acc, cur_t, wm, wn, lane);
}

// ---------------- reduce slabs + bias (+relu) ----------------
__global__ void reduce_kernel(const float* __restrict__ bias,
                              float* __restrict__ out, int do_relu) {
    int i = blockIdx.x * blockDim.x + threadIdx.x;
    const int n4 = N_NODES * D / 4;
    if (i >= n4) return;
    const float4* p4 = (const float4*)g_partial;
    float4 s = p4[i];
    #pragma unroll
    for (int k = 1; k < NSLAB; k++) {
        float4 t = p4[i + (size_t)k * n4];
        s.x += t.x; s.y += t.y; s.z += t.z; s.w += t.w;
    }
    float4 b = ((const float4*)bias)[i & 31];
    s.x += b.x; s.y += b.y; s.z += b.z; s.w += b.w;
    if (do_relu) {
        s.x = fmaxf(s.x, 0.f); s.y = fmaxf(s.y, 0.f);
        s.z = fmaxf(s.z, 0.f); s.w = fmaxf(s.w, 0.f);
    }
    ((float4*)out)[i] = s;
}

// ---------------- scoring: warp per batch item ----------------
__global__ void score_kernel(const int* __restrict__ batch,
                             const float* __restrict__ xn,
                             const float* __restrict__ rels,
                             float* __restrict__ out) {
    int w = (blockIdx.x * blockDim.x + threadIdx.x) >> 5;
    int lane = threadIdx.x & 31;
    if (w >= N_BATCH) return;
    int bs = batch[w*3+0], bp = batch[w*3+1], bo = batch[w*3+2];
    float4 a = ((const float4*)(xn + (size_t)bs * D))[lane];
    float4 r = ((const float4*)(rels + (size_t)bp * D))[lane];
    float4 c = ((const float4*)(xn + (size_t)bo * D))[lane];
    float s = a.x*r.x*c.x + a.y*r.y*c.y + a.z*r.z*c.z + a.w*r.w*c.w;
    #pragma unroll
    for (int o = 16; o; o >>= 1) s += __shfl_xor_sync(0xffffffffu, s, o);
    if (lane == 0) out[w] = s;
}

// ---------------- launch ----------------
extern "C" void kernel_launch(void* const* d_in, const int* in_sizes, int n_in,
                              void* d_out, int out_size) {
    const int*   graph = (const int*)d_in[0];
    const int*   batch = (const int*)d_in[1];
    const float* x0    = (const float*)d_in[2];
    const float* W1    = (const float*)d_in[3];
    const float* b1    = (const float*)d_in[4];
    const float* W2    = (const float*)d_in[5];
    const float* b2    = (const float*)d_in[6];
    const float* rels  = (const float*)d_in[7];
    float* out = (float*)d_out;

    void *p_h1 = nullptr, *p_h2 = nullptr, *p_bt1 = nullptr, *p_bt2 = nullptr;
    cudaGetSymbolAddress(&p_h1, g_h1);
    cudaGetSymbolAddress(&p_h2, g_h2);
    cudaGetSymbolAddress(&p_bt1, g_Bt1);
    cudaGetSymbolAddress(&p_bt2, g_Bt2);
    float* h1 = (float*)p_h1;
    float* h2 = (float*)p_h2;
    u16* bt1 = (u16*)p_bt1;
    u16* bt2 = (u16*)p_bt2;

    cudaFuncSetAttribute(layer_mega_kernel,
                         cudaFuncAttributeMaxDynamicSharedMemorySize, SMEM_TOT);

    const int zp_grid = (NSLAB * N_NODES * D / 4 + 255) / 256;
    const int rd_grid = (N_NODES * D / 4 + 255) / 256;

    // launches 1-3: W conversions + partial zero (layer kernel lands in slot 4)
    convert_w_kernel<<<R_AUG, 256>>>(W1, bt1);
    convert_w_kernel<<<R_AUG, 256>>>(W2, bt2);
    zero_partial_kernel<<<zp_grid, 256>>>();

    // layer 1 (builds CSR internally via grid barriers; 148 CTAs = 1/SM)
    layer_mega_kernel<<<NCTA, 256, SMEM_TOT>>>(x0, graph, bt1, 1);
    reduce_kernel<<<rd_grid, 256>>>(b1, h1, 1);

    // layer 2
    zero_partial_kernel<<<zp_grid, 256>>>();
    layer_mega_kernel<<<NCTA, 256, SMEM_TOT>>>(h1, graph, bt2, 0);
    reduce_kernel<<<rd_grid, 256>>>(b2, h2, 0);

    // scoring
    score_kernel<<<(N_BATCH * 32) / 256, 256>>>(batch, h2, rels, out);
}

// round 14
// speedup vs baseline: 1.3022x; 1.3022x over previous
#include <cuda_runtime.h>
#include <cuda_fp16.h>

// ---------------- problem constants ----------------
#define N_NODES 10000
#define N_RELS  50
#define R_AUG   101                    // 2*N_RELS + 1
#define D       128
#define N_EDGES 320000
#define E_AUG   (2*N_EDGES + N_NODES)  // 650000
#define N_SEG   (R_AUG * N_NODES)      // 1010000
#define N_BATCH 65536

// persistent layer config: 3 CTAs/SM, M-tile 64
#define TM      64
#define NTILES  ((N_NODES + TM - 1) / TM)          // 157
#define NITEMS  (NTILES * R_AUG)                   // 15857
#define NCTA    444
#define WPC     ((NITEMS + NCTA - 1) / NCTA)       // 36
#define NSLAB   4
#define SEG_CHUNK ((N_SEG + NCTA - 1) / NCTA)      // 2275

// fp16 tile row stride: 128 + 8 pad = 136 halves = 272 bytes
#define TS      272
#define APLANE  (64 * TS)                           // 17408
#define BPLANE  (128 * TS)                          // 34816

// edge-staging capacity (ints)
#define ECAP    1024

// smem layout (bytes)
#define OFF_AH   0                                  // A hi [64][136]
#define OFF_AL   APLANE                             // A lo
#define OFF_B    (2*APLANE)                         // B fp16 [128][136]
#define OFF_EDGE (2*APLANE + BPLANE)                // staged edge srcs (ECAP ints)
#define OFF_RP   (OFF_EDGE + ECAP*4)                // staged rowptr (65 ints)
#define SMEM_TOT (OFF_RP + 272)                     // 74,000 B -> 3/SM

typedef unsigned long long u64;
typedef unsigned int u32;
typedef unsigned short u16;

// ---------------- static device scratch ----------------
__device__ int   g_deg[N_SEG];
__device__ int   g_rowptr[N_SEG + 1];
__device__ int   g_cursor[N_SEG];
__device__ int   g_ctasum[NCTA];
__device__ int   g_csr[E_AUG];                         // src only
__device__ u16   g_Bt1[(size_t)R_AUG * 16384];         // layer1 W fp16, row=n col=k
__device__ u16   g_Bt2[(size_t)R_AUG * 16384];         // layer2 W
__device__ float g_h1[N_NODES * D];
__device__ float g_h2[N_NODES * D];
__device__ float g_partial[(size_t)NSLAB * N_NODES * D];
__device__ unsigned g_bcnt[8];                         // grid barrier counters (self-reset)
__device__ unsigned g_brel[8];                         // grid barrier release epochs (monotonic)

// ---------------- small helpers ----------------
__device__ __forceinline__ u32 smem_u32(const void* p) {
    u32 a;
    asm("{ .reg .u64 t; cvta.to.shared.u64 t, %1; cvt.u32.u64 %0, t; }" : "=r"(a) : "l"(p));
    return a;
}
__device__ __forceinline__ u16 f2h(float v) {
    u16 r; asm("cvt.rn.f16.f32 %0, %1;" : "=h"(r) : "f"(v)); return r;
}
__device__ __forceinline__ float h2f(u16 v) {
    float r; asm("cvt.f32.f16 %0, %1;" : "=f"(r) : "h"(v)); return r;
}

#define LDSM4(r, addr)                                                          \
    asm volatile("ldmatrix.sync.aligned.m8n8.x4.shared.b16 {%0,%1,%2,%3}, [%4];"\
        : "=r"((r)[0]), "=r"((r)[1]), "=r"((r)[2]), "=r"((r)[3]) : "r"(addr))

#define MMA16816(c, a, b0_, b1_)                                                \
    asm volatile("mma.sync.aligned.m16n8k16.row.col.f32.f16.f16.f32 "           \
        "{%0,%1,%2,%3}, {%4,%5,%6,%7}, {%8,%9}, {%0,%1,%2,%3};"                 \
        : "+f"((c)[0]), "+f"((c)[1]), "+f"((c)[2]), "+f"((c)[3])                \
        : "r"((a)[0]), "r"((a)[1]), "r"((a)[2]), "r"((a)[3]), "r"(b0_), "r"(b1_))

#define CP_ASYNC16(dst, src)                                                    \
    asm volatile("cp.async.cg.shared.global [%0], [%1], 16;" :: "r"(dst), "l"(src))
#define CP_COMMIT() asm volatile("cp.async.commit_group;" ::: "memory")
#define CP_WAIT0()  asm volatile("cp.async.wait_group 0;" ::: "memory")

// ---- replay-safe software grid barrier (all NCTA CTAs co-resident: 3/SM) ----
__device__ __forceinline__ void grid_bar(int slot) {
    __threadfence();
    __syncthreads();
    if (threadIdx.x == 0) {
        volatile unsigned* rel = (volatile unsigned*)&g_brel[slot];
        unsigned e0 = *rel;
        unsigned t = atomicAdd(&g_bcnt[slot], 1u);
        if (t == NCTA - 1) {
            g_bcnt[slot] = 0;
            __threadfence();
            atomicAdd(&g_brel[slot], 1u);
        } else {
            while (*rel == e0) { }
        }
        __threadfence();
    }
    __syncthreads();
}

// ---- block exclusive scan over 256 ints; returns exclusive, sets total ----
__device__ __forceinline__ int block_excl_scan(int v, int* ssc, int& total) {
    int lane = threadIdx.x & 31, w = threadIdx.x >> 5;
    int x = v;
    #pragma unroll
    for (int o = 1; o < 32; o <<= 1) {
        int y = __shfl_up_sync(0xffffffffu, x, o);
        if (lane >= o) x += y;
    }
    if (lane == 31) ssc[w] = x;
    __syncthreads();
    if (w == 0) {
        int tval = (lane < 8) ? ssc[lane] : 0;
        #pragma unroll
        for (int o = 1; o < 8; o <<= 1) {
            int y = __shfl_up_sync(0xffffffffu, tval, o);
            if (lane >= o) tval += y;
        }
        if (lane < 8) ssc[lane] = tval;    // inclusive warp totals
    }
    __syncthreads();
    int wbase = (w > 0) ? ssc[w - 1] : 0;
    total = ssc[7];
    __syncthreads();
    return wbase + x - v;
}

__device__ __forceinline__ void aug_edge(const int* __restrict__ g, int e,
                                         int& seg, int& src) {
    if (e < N_EDGES) {
        int s = g[e*3+0], p = g[e*3+1], o = g[e*3+2];
        seg = p * N_NODES + o;  src = s;
    } else if (e < 2*N_EDGES) {
        int e2 = e - N_EDGES;
        int s = g[e2*3+0], p = g[e2*3+1], o = g[e2*3+2];
        seg = (p + N_RELS) * N_NODES + s;  src = o;
    } else {
        int i = e - 2*N_EDGES;
        seg = 2*N_RELS*N_NODES + i;  src = i;
    }
}

// ---------------- W -> fp16 B^T plane (row=n, col=k) ----------------
__global__ void convert_w_kernel(const float* __restrict__ W, u16* __restrict__ Bt) {
    int r = blockIdx.x;
    const float* Wr = W + (size_t)r * (D * D);
    u16* B = Bt + (size_t)r * 16384;
    for (int idx = threadIdx.x; idx < D * D; idx += blockDim.x) {
        int k = idx >> 7, n = idx & 127;
        B[n * D + k] = f2h(Wr[k * D + n]);
    }
}

__global__ void zero_partial_kernel() {
    int i = blockIdx.x * blockDim.x + threadIdx.x;
    const int n4 = NSLAB * N_NODES * D / 4;
    if (i < n4) ((float4*)g_partial)[i] = make_float4(0.f, 0.f, 0.f, 0.f);
}

// ---------------- flush register accumulators to a partial slab ----------------
__device__ __forceinline__ void flush_acc(float acc[2][4][4], int cur_t,
                                          int warp, int lane) {
    int slab_i = blockIdx.x - (cur_t * R_AUG) / WPC;
    float* slab = g_partial + (size_t)slab_i * (N_NODES * D);
    int wm = warp & 1, wn = warp >> 1;
    int r0 = cur_t * TM + wm * 32 + (lane >> 2);
    int cb = wn * 32 + (lane & 3) * 2;
    #pragma unroll
    for (int mf = 0; mf < 2; mf++) {
        int rowA = r0 + mf * 16;
        int rowB = rowA + 8;
        #pragma unroll
        for (int nf = 0; nf < 4; nf++) {
            int col = cb + nf * 8;
            if (rowA < N_NODES)
                *(float2*)(slab + (size_t)rowA * D + col) =
                    make_float2(acc[mf][nf][0], acc[mf][nf][1]);
            if (rowB < N_NODES)
                *(float2*)(slab + (size_t)rowB * D + col) =
                    make_float2(acc[mf][nf][2], acc[mf][nf][3]);
        }
    }
}

// ---- cp.async prefetch of one relation's fp16 B tile (single plane) ----
__device__ __forceinline__ void prefetch_B(u32 smbuf, const u16* __restrict__ Bt, int r) {
    const char* src_base = (const char*)(Bt + (size_t)r * 16384);
    int tid = threadIdx.x;
    #pragma unroll
    for (int q = 0; q < 8; q++) {
        int idx = tid + q * 256;           // 0..2047 16B chunks
        int row = idx >> 4, c16 = idx & 15;
        u32 dst = smbuf + row * TS + c16 * 16;
        const char* src = src_base + row * 256 + c16 * 16;
        CP_ASYNC16(dst, src);
    }
}

// ---------------- persistent mega kernel: (optional CSR build) + layer ----------------
extern "C" __global__ void __launch_bounds__(256, 3)
layer_mega_kernel(const float* __restrict__ x, const int* __restrict__ graph,
                  const u16* __restrict__ Bt, int build_csr) {
    extern __shared__ char smem[];
    __shared__ int ssc[16];
    __shared__ int sbase;
    u32 smb = smem_u32(smem);
    int* sEdge = (int*)(smem + OFF_EDGE);
    int* sRp   = (int*)(smem + OFF_RP);

    int tid  = threadIdx.x;
    int bid  = blockIdx.x;
    int gtid = bid * 256 + tid;
    const int gstride = NCTA * 256;

    // ================= CSR build (layer-1 instance only) =================
    if (build_csr) {
        for (int i = gtid; i < N_SEG; i += gstride) g_deg[i] = 0;
        grid_bar(0);
        for (int e = gtid; e < E_AUG; e += gstride) {
            int seg, src;
            aug_edge(graph, e, seg, src);
            atomicAdd(&g_deg[seg], 1);
        }
        grid_bar(1);
        int s0 = bid * SEG_CHUNK;
        int s1 = min(s0 + SEG_CHUNK, N_SEG);
        {
            int lsum = 0;
            for (int i = s0 + tid; i < s1; i += 256) lsum += g_deg[i];
            #pragma unroll
            for (int o = 16; o; o >>= 1) lsum += __shfl_xor_sync(0xffffffffu, lsum, o);
            if ((tid & 31) == 0) ssc[tid >> 5] = lsum;
            __syncthreads();
            if (tid < 8) {
                int v = ssc[tid];
                #pragma unroll
                for (int o = 4; o; o >>= 1) v += __shfl_xor_sync(0xffu, v, o);
                if (tid == 0) g_ctasum[bid] = v;
            }
            __syncthreads();
        }
        grid_bar(2);
        {
            int va = 0, vp = 0;
            if (tid < NCTA / 2) {
                va = g_ctasum[2 * tid];
                vp = va + g_ctasum[2 * tid + 1];
            }
            int tot;
            int ex = block_excl_scan(vp, ssc, tot);
            if (2 * tid == bid) sbase = ex;
            if (2 * tid + 1 == bid) sbase = ex + va;
            __syncthreads();
            int run = sbase;
            const int nchunk = (SEG_CHUNK + 255) / 256;
            for (int c = 0; c < nchunk; c++) {
                int gi = s0 + c * 256 + tid;
                int dv = (gi < s1) ? g_deg[gi] : 0;
                int ctot;
                int cex = block_excl_scan(dv, ssc, ctot);
                if (gi < s1) {
                    int rp = run + cex;
                    g_rowptr[gi] = rp;
                    g_cursor[gi] = rp;
                }
                run += ctot;
            }
            if (bid == NCTA - 1 && tid == 0) g_rowptr[N_SEG] = E_AUG;
        }
        grid_bar(3);
        for (int e = gtid; e < E_AUG; e += gstride) {
            int seg, src;
            aug_edge(graph, e, seg, src);
            int pos = atomicAdd(&g_cursor[seg], 1);
            g_csr[pos] = src;
        }
        grid_bar(4);
    }

    // ================= layer items =================
    int warp = tid >> 5, lane = tid & 31;
    int wm = warp & 1, wn = warp >> 1;

    // ldmatrix per-lane row offsets (bytes) within a tile
    u32 rowa = (u32)(wm * 32 + (lane & 15)) * TS + (u32)((lane >> 4) << 3) * 2;
    u32 rowb = (u32)(wn * 32 + ((lane >> 4) << 3) + (lane & 7)) * TS
             + (u32)(((lane >> 3) & 1) << 3) * 2;
    u32 aHb = smb + OFF_AH + rowa, aLb = smb + OFF_AL + rowa;
    u32 bHb = smb + OFF_B + rowb;

    int bsub = tid & 3;            // 32-dim chunk
    int brow = tid >> 2;           // row 0..63

    float acc[2][4][4];
    #pragma unroll
    for (int i = 0; i < 2; i++)
        #pragma unroll
        for (int j = 0; j < 4; j++)
            #pragma unroll
            for (int q = 0; q < 4; q++) acc[i][j][q] = 0.f;

    int i0 = bid * WPC;
    int i1 = min(i0 + WPC, NITEMS);
    if (i0 >= i1) return;

    int cur_t = -1;

    for (int it = i0; it < i1; ++it) {
        int t = it / R_AUG;
        int r = it - t * R_AUG;
        int tb = t * TM;
        int nrows = min(TM, N_NODES - tb);
        int segbase = r * N_NODES + tb;

        if (t != cur_t) {
            if (cur_t >= 0) {
                flush_acc(acc, cur_t, warp, lane);
                #pragma unroll
                for (int i = 0; i < 2; i++)
                    #pragma unroll
                    for (int j = 0; j < 4; j++)
                        #pragma unroll
                        for (int q = 0; q < 4; q++) acc[i][j][q] = 0.f;
            }
            cur_t = t;
        }

        __syncthreads();   // previous GEMM done reading A & B tiles

        // ---- (A) kick B prefetch (buffer free now), overlaps the build ----
        prefetch_B(smb + OFF_B, Bt, r);
        CP_COMMIT();

        // ---- (B) stage rowptr (coalesced) ----
        if (tid <= nrows) sRp[tid] = g_rowptr[segbase + tid];
        __syncthreads();

        // ---- (C) stage edge srcs for the whole item (contiguous span) ----
        int e0 = sRp[0], e1 = sRp[nrows];
        int nE = e1 - e0;
        bool staged = (nE <= ECAP);
        if (staged) {
            for (int j = tid; j < nE; j += 256) sEdge[j] = g_csr[e0 + j];
        }
        __syncthreads();

        // ---- (D) build + convert A tiles, register-resident, no atomics ----
        {
            float4 a[8];
            #pragma unroll
            for (int q = 0; q < 8; q++) a[q] = make_float4(0.f, 0.f, 0.f, 0.f);
            int deg = 0;
            if (brow < nrows) {
                int rs = sRp[brow], re = sRp[brow + 1];
                deg = re - rs;
                if (staged) {
                    #pragma unroll 2
                    for (int j = rs - e0; j < re - e0; ++j) {
                        int src = sEdge[j];
                        const float4* v = (const float4*)(x + (size_t)src * D + (bsub << 5));
                        #pragma unroll
                        for (int q = 0; q < 8; q++) {
                            float4 w = v[q];
                            a[q].x += w.x; a[q].y += w.y; a[q].z += w.z; a[q].w += w.w;
                        }
                    }
                } else {
                    for (int j = rs; j < re; ++j) {
                        int src = g_csr[j];
                        const float4* v = (const float4*)(x + (size_t)src * D + (bsub << 5));
                        #pragma unroll
                        for (int q = 0; q < 8; q++) {
                            float4 w = v[q];
                            a[q].x += w.x; a[q].y += w.y; a[q].z += w.z; a[q].w += w.w;
                        }
                    }
                }
            }
            float nrm = 1.0f / fmaxf((float)deg, 1.0f);
            u32* AH = (u32*)(smem + OFF_AH + brow * TS + (bsub << 6));
            u32* AL = (u32*)(smem + OFF_AL + brow * TS + (bsub << 6));
            #pragma unroll
            for (int q = 0; q < 8; q++) {
                float v0 = a[q].x * nrm, v1 = a[q].y * nrm;
                float v2 = a[q].z * nrm, v3 = a[q].w * nrm;
                u16 h0 = f2h(v0), h1 = f2h(v1), h2 = f2h(v2), h3 = f2h(v3);
                u16 l0 = f2h(v0 - h2f(h0)), l1 = f2h(v1 - h2f(h1));
                u16 l2 = f2h(v2 - h2f(h2)), l3 = f2h(v3 - h2f(h3));
                AH[q*2+0] = (u32)h0 | ((u32)h1 << 16);
                AH[q*2+1] = (u32)h2 | ((u32)h3 << 16);
                AL[q*2+0] = (u32)l0 | ((u32)l1 << 16);
                AL[q*2+1] = (u32)l2 | ((u32)l3 << 16);
            }
        }

        // ---- (E) wait B, then 64x128x128 GEMM, 2-term fp16 split ----
        CP_WAIT0();
        __syncthreads();

        #pragma unroll
        for (int ks = 0; ks < 8; ks++) {
            u32 k2 = (u32)ks * 32;                  // k0 * 2 bytes
            u32 aH0[4], aH1[4], aL0[4], aL1[4];
            LDSM4(aH0, aHb + k2);
            LDSM4(aH1, aHb + 16 * TS + k2);
            LDSM4(aL0, aLb + k2);
            LDSM4(aL1, aLb + 16 * TS + k2);
            #pragma unroll
            for (int nh = 0; nh < 2; nh++) {
                u32 bH[4];
                LDSM4(bH, bHb + (u32)nh * 16 * TS + k2);
                int n0 = nh * 2, n1 = nh * 2 + 1;
                MMA16816(acc[0][n0], aH0, bH[0], bH[1]);
                MMA16816(acc[0][n0], aL0, bH[0], bH[1]);
                MMA16816(acc[1][n0], aH1, bH[0], bH[1]);
                MMA16816(acc[1][n0], aL1, bH[0], bH[1]);
                MMA16816(acc[0][n1], aH0, bH[2], bH[3]);
                MMA16816(acc[0][n1], aL0, bH[2], bH[3]);
                MMA16816(acc[1][n1], aH1, bH[2], bH[3]);
                MMA16816(acc[1][n1], aL1, bH[2], bH[3]);
            }
        }
    }

    if (cur_t >= 0) flush_acc(acc, cur_t, warp, lane);
}

// ---------------- reduce slabs + bias (+relu) ----------------
__global__ void reduce_kernel(const float* __restrict__ bias,
                              float* __restrict__ out, int do_relu) {
    int i = blockIdx.x * blockDim.x + threadIdx.x;
    const int n4 = N_NODES * D / 4;
    if (i >= n4) return;
    const float4* p4 = (const float4*)g_partial;
    float4 s = p4[i];
    #pragma unroll
    for (int k = 1; k < NSLAB; k++) {
        float4 t = p4[i + (size_t)k * n4];
        s.x += t.x; s.y += t.y; s.z += t.z; s.w += t.w;
    }
    float4 b = ((const float4*)bias)[i & 31];
    s.x += b.x; s.y += b.y; s.z += b.z; s.w += b.w;
    if (do_relu) {
        s.x = fmaxf(s.x, 0.f); s.y = fmaxf(s.y, 0.f);
        s.z = fmaxf(s.z, 0.f); s.w = fmaxf(s.w, 0.f);
    }
    ((float4*)out)[i] = s;
}

// ---------------- scoring: warp per batch item ----------------
__global__ void score_kernel(const int* __restrict__ batch,
                             const float* __restrict__ xn,
                             const float* __restrict__ rels,
                             float* __restrict__ out) {
    int w = (blockIdx.x * blockDim.x + threadIdx.x) >> 5;
    int lane = threadIdx.x & 31;
    if (w >= N_BATCH) return;
    int bs = batch[w*3+0], bp = batch[w*3+1], bo = batch[w*3+2];
    float4 a = ((const float4*)(xn + (size_t)bs * D))[lane];
    float4 r = ((const float4*)(rels + (size_t)bp * D))[lane];
    float4 c = ((const float4*)(xn + (size_t)bo * D))[lane];
    float s = a.x*r.x*c.x + a.y*r.y*c.y + a.z*r.z*c.z + a.w*r.w*c.w;
    #pragma unroll
    for (int o = 16; o; o >>= 1) s += __shfl_xor_sync(0xffffffffu, s, o);
    if (lane == 0) out[w] = s;
}

// ---------------- launch ----------------
extern "C" void kernel_launch(void* const* d_in, const int* in_sizes, int n_in,
                              void* d_out, int out_size) {
    const int*   graph = (const int*)d_in[0];
    const int*   batch = (const int*)d_in[1];
    const float* x0    = (const float*)d_in[2];
    const float* W1    = (const float*)d_in[3];
    const float* b1    = (const float*)d_in[4];
    const float* W2    = (const float*)d_in[5];
    const float* b2    = (const float*)d_in[6];
    const float* rels  = (const float*)d_in[7];
    float* out = (float*)d_out;

    void *p_h1 = nullptr, *p_h2 = nullptr, *p_bt1 = nullptr, *p_bt2 = nullptr;
    cudaGetSymbolAddress(&p_h1, g_h1);
    cudaGetSymbolAddress(&p_h2, g_h2);
    cudaGetSymbolAddress(&p_bt1, g_Bt1);
    cudaGetSymbolAddress(&p_bt2, g_Bt2);
    float* h1 = (float*)p_h1;
    float* h2 = (float*)p_h2;
    u16* bt1 = (u16*)p_bt1;
    u16* bt2 = (u16*)p_bt2;

    cudaFuncSetAttribute(layer_mega_kernel,
                         cudaFuncAttributeMaxDynamicSharedMemorySize, SMEM_TOT);

    const int zp_grid = (NSLAB * N_NODES * D / 4 + 255) / 256;
    const int rd_grid = (N_NODES * D / 4 + 255) / 256;

    // launches 1-3: W conversions + partial zero (layer kernel lands in slot 4)
    convert_w_kernel<<<R_AUG, 256>>>(W1, bt1);
    convert_w_kernel<<<R_AUG, 256>>>(W2, bt2);
    zero_partial_kernel<<<zp_grid, 256>>>();

    // layer 1 (builds CSR internally via grid barriers; 444 CTAs = 3/SM)
    layer_mega_kernel<<<NCTA, 256, SMEM_TOT>>>(x0, graph, bt1, 1);
    reduce_kernel<<<rd_grid, 256>>>(b1, h1, 1);

    // layer 2
    zero_partial_kernel<<<zp_grid, 256>>>();
    layer_mega_kernel<<<NCTA, 256, SMEM_TOT>>>(h1, graph, bt2, 0);
    reduce_kernel<<<rd_grid, 256>>>(b2, h2, 0);

    // scoring
    score_kernel<<<(N_BATCH * 32) / 256, 256>>>(batch, h2, rels, out);
}

// round 15
// speedup vs baseline: 1.3666x; 1.0495x over previous
#include <cuda_runtime.h>
#include <cuda_fp16.h>

// ---------------- problem constants ----------------
#define N_NODES 10000
#define N_RELS  50
#define R_AUG   101                    // 2*N_RELS + 1
#define D       128
#define N_EDGES 320000
#define E_AUG   (2*N_EDGES + N_NODES)  // 650000
#define N_SEG   (R_AUG * N_NODES)      // 1010000
#define N_BATCH 65536

// persistent layer config: 2 CTAs/SM, M-tile 128
#define TM      128
#define NTILES  ((N_NODES + TM - 1) / TM)          // 79
#define NITEMS  (NTILES * R_AUG)                   // 7979
#define NCTA    296
#define WPC     ((NITEMS + NCTA - 1) / NCTA)       // 27
#define NSLAB   5
#define SEG_CHUNK ((N_SEG + NCTA - 1) / NCTA)      // 3413

// fp16 tile row stride: 128 + 8 pad = 136 halves = 272 bytes
#define TS      272
#define APLANE  (128 * TS)                          // 34816
#define BPLANE  (128 * TS)                          // 34816

// edge-staging capacity (ints)
#define ECAP    1024

// smem layout (bytes)
#define OFF_AH   0                                  // A hi [128][136]
#define OFF_AL   APLANE                             // A lo
#define OFF_B    (2*APLANE)                         // B fp16 [128][136]
#define OFF_EDGE (2*APLANE + BPLANE)                // staged edge srcs (ECAP ints)
#define OFF_RP   (OFF_EDGE + ECAP*4)                // staged rowptr (129 ints)
#define SMEM_TOT (OFF_RP + 544)                     // 109,088 B -> 2/SM

typedef unsigned long long u64;
typedef unsigned int u32;
typedef unsigned short u16;

// ---------------- static device scratch ----------------
__device__ int   g_deg[N_SEG];
__device__ int   g_rowptr[N_SEG + 1];
__device__ int   g_cursor[N_SEG];
__device__ int   g_ctasum[NCTA];
__device__ int   g_csr[E_AUG];                         // src only
__device__ u16   g_Bt1[(size_t)R_AUG * 16384];         // layer1 W fp16, row=n col=k
__device__ u16   g_Bt2[(size_t)R_AUG * 16384];         // layer2 W
__device__ float g_h1[N_NODES * D];
__device__ float g_h2[N_NODES * D];
__device__ float g_partial[(size_t)NSLAB * N_NODES * D];
__device__ unsigned g_bcnt[8];                         // grid barrier counters (self-reset)
__device__ unsigned g_brel[8];                         // grid barrier release epochs (monotonic)

// ---------------- small helpers ----------------
__device__ __forceinline__ u32 smem_u32(const void* p) {
    u32 a;
    asm("{ .reg .u64 t; cvta.to.shared.u64 t, %1; cvt.u32.u64 %0, t; }" : "=r"(a) : "l"(p));
    return a;
}
__device__ __forceinline__ u16 f2h(float v) {
    u16 r; asm("cvt.rn.f16.f32 %0, %1;" : "=h"(r) : "f"(v)); return r;
}
__device__ __forceinline__ float h2f(u16 v) {
    float r; asm("cvt.f32.f16 %0, %1;" : "=f"(r) : "h"(v)); return r;
}

#define LDSM4(r, addr)                                                          \
    asm volatile("ldmatrix.sync.aligned.m8n8.x4.shared.b16 {%0,%1,%2,%3}, [%4];"\
        : "=r"((r)[0]), "=r"((r)[1]), "=r"((r)[2]), "=r"((r)[3]) : "r"(addr))

#define MMA16816(c, a, b0_, b1_)                                                \
    asm volatile("mma.sync.aligned.m16n8k16.row.col.f32.f16.f16.f32 "           \
        "{%0,%1,%2,%3}, {%4,%5,%6,%7}, {%8,%9}, {%0,%1,%2,%3};"                 \
        : "+f"((c)[0]), "+f"((c)[1]), "+f"((c)[2]), "+f"((c)[3])                \
        : "r"((a)[0]), "r"((a)[1]), "r"((a)[2]), "r"((a)[3]), "r"(b0_), "r"(b1_))

#define CP_ASYNC16(dst, src)                                                    \
    asm volatile("cp.async.cg.shared.global [%0], [%1], 16;" :: "r"(dst), "l"(src))
#define CP_COMMIT() asm volatile("cp.async.commit_group;" ::: "memory")
#define CP_WAIT0()  asm volatile("cp.async.wait_group 0;" ::: "memory")

// ---- replay-safe software grid barrier (all NCTA CTAs co-resident: 2/SM) ----
__device__ __forceinline__ void grid_bar(int slot) {
    __threadfence();
    __syncthreads();
    if (threadIdx.x == 0) {
        volatile unsigned* rel = (volatile unsigned*)&g_brel[slot];
        unsigned e0 = *rel;
        unsigned t = atomicAdd(&g_bcnt[slot], 1u);
        if (t == NCTA - 1) {
            g_bcnt[slot] = 0;
            __threadfence();
            atomicAdd(&g_brel[slot], 1u);
        } else {
            while (*rel == e0) { }
        }
        __threadfence();
    }
    __syncthreads();
}

// ---- block exclusive scan over 256 ints; returns exclusive, sets total ----
__device__ __forceinline__ int block_excl_scan(int v, int* ssc, int& total) {
    int lane = threadIdx.x & 31, w = threadIdx.x >> 5;
    int x = v;
    #pragma unroll
    for (int o = 1; o < 32; o <<= 1) {
        int y = __shfl_up_sync(0xffffffffu, x, o);
        if (lane >= o) x += y;
    }
    if (lane == 31) ssc[w] = x;
    __syncthreads();
    if (w == 0) {
        int tval = (lane < 8) ? ssc[lane] : 0;
        #pragma unroll
        for (int o = 1; o < 8; o <<= 1) {
            int y = __shfl_up_sync(0xffffffffu, tval, o);
            if (lane >= o) tval += y;
        }
        if (lane < 8) ssc[lane] = tval;    // inclusive warp totals
    }
    __syncthreads();
    int wbase = (w > 0) ? ssc[w - 1] : 0;
    total = ssc[7];
    __syncthreads();
    return wbase + x - v;
}

__device__ __forceinline__ void aug_edge(const int* __restrict__ g, int e,
                                         int& seg, int& src) {
    if (e < N_EDGES) {
        int s = g[e*3+0], p = g[e*3+1], o = g[e*3+2];
        seg = p * N_NODES + o;  src = s;
    } else if (e < 2*N_EDGES) {
        int e2 = e - N_EDGES;
        int s = g[e2*3+0], p = g[e2*3+1], o = g[e2*3+2];
        seg = (p + N_RELS) * N_NODES + s;  src = o;
    } else {
        int i = e - 2*N_EDGES;
        seg = 2*N_RELS*N_NODES + i;  src = i;
    }
}

// ---------------- W -> fp16 B^T plane (row=n, col=k) ----------------
__global__ void convert_w_kernel(const float* __restrict__ W, u16* __restrict__ Bt) {
    int r = blockIdx.x;
    const float* Wr = W + (size_t)r * (D * D);
    u16* B = Bt + (size_t)r * 16384;
    for (int idx = threadIdx.x; idx < D * D; idx += blockDim.x) {
        int k = idx >> 7, n = idx & 127;
        B[n * D + k] = f2h(Wr[k * D + n]);
    }
}

__global__ void zero_partial_kernel() {
    int i = blockIdx.x * blockDim.x + threadIdx.x;
    const int n4 = NSLAB * N_NODES * D / 4;
    if (i < n4) ((float4*)g_partial)[i] = make_float4(0.f, 0.f, 0.f, 0.f);
}

// ---------------- flush register accumulators to a partial slab ----------------
// warp tile 32x64: wm = warp&3 (m), wn = warp>>2 (n)
__device__ __forceinline__ void flush_acc(float acc[2][8][4], int cur_t,
                                          int wm, int wn, int lane) {
    int slab_i = blockIdx.x - (cur_t * R_AUG) / WPC;
    float* slab = g_partial + (size_t)slab_i * (N_NODES * D);
    int r0 = cur_t * TM + wm * 32 + (lane >> 2);
    int cb = wn * 64 + (lane & 3) * 2;
    #pragma unroll
    for (int mf = 0; mf < 2; mf++) {
        int rowA = r0 + mf * 16;
        int rowB = rowA + 8;
        #pragma unroll
        for (int nf = 0; nf < 8; nf++) {
            int col = cb + nf * 8;
            if (rowA < N_NODES)
                *(float2*)(slab + (size_t)rowA * D + col) =
                    make_float2(acc[mf][nf][0], acc[mf][nf][1]);
            if (rowB < N_NODES)
                *(float2*)(slab + (size_t)rowB * D + col) =
                    make_float2(acc[mf][nf][2], acc[mf][nf][3]);
        }
    }
}

// ---- cp.async prefetch of one relation's fp16 B tile (single plane) ----
__device__ __forceinline__ void prefetch_B(u32 smbuf, const u16* __restrict__ Bt, int r) {
    const char* src_base = (const char*)(Bt + (size_t)r * 16384);
    int tid = threadIdx.x;
    #pragma unroll
    for (int q = 0; q < 8; q++) {
        int idx = tid + q * 256;           // 0..2047 16B chunks
        int row = idx >> 4, c16 = idx & 15;
        u32 dst = smbuf + row * TS + c16 * 16;
        const char* src = src_base + row * 256 + c16 * 16;
        CP_ASYNC16(dst, src);
    }
}

// ---------------- persistent mega kernel: (optional CSR build) + layer ----------------
extern "C" __global__ void __launch_bounds__(256, 2)
layer_mega_kernel(const float* __restrict__ x, const int* __restrict__ graph,
                  const u16* __restrict__ Bt, int build_csr) {
    extern __shared__ char smem[];
    __shared__ int ssc[16];
    __shared__ int sbase;
    u32 smb = smem_u32(smem);
    int* sEdge = (int*)(smem + OFF_EDGE);
    int* sRp   = (int*)(smem + OFF_RP);

    int tid  = threadIdx.x;
    int bid  = blockIdx.x;
    int gtid = bid * 256 + tid;
    const int gstride = NCTA * 256;

    // ================= CSR build (layer-1 instance only) =================
    if (build_csr) {
        for (int i = gtid; i < N_SEG; i += gstride) g_deg[i] = 0;
        grid_bar(0);
        for (int e = gtid; e < E_AUG; e += gstride) {
            int seg, src;
            aug_edge(graph, e, seg, src);
            atomicAdd(&g_deg[seg], 1);
        }
        grid_bar(1);
        int s0 = bid * SEG_CHUNK;
        int s1 = min(s0 + SEG_CHUNK, N_SEG);
        {
            int lsum = 0;
            for (int i = s0 + tid; i < s1; i += 256) lsum += g_deg[i];
            #pragma unroll
            for (int o = 16; o; o >>= 1) lsum += __shfl_xor_sync(0xffffffffu, lsum, o);
            if ((tid & 31) == 0) ssc[tid >> 5] = lsum;
            __syncthreads();
            if (tid < 8) {
                int v = ssc[tid];
                #pragma unroll
                for (int o = 4; o; o >>= 1) v += __shfl_xor_sync(0xffu, v, o);
                if (tid == 0) g_ctasum[bid] = v;
            }
            __syncthreads();
        }
        grid_bar(2);
        {
            int va = 0, vp = 0;
            if (tid < NCTA / 2) {
                va = g_ctasum[2 * tid];
                vp = va + g_ctasum[2 * tid + 1];
            }
            int tot;
            int ex = block_excl_scan(vp, ssc, tot);
            if (2 * tid == bid) sbase = ex;
            if (2 * tid + 1 == bid) sbase = ex + va;
            __syncthreads();
            int run = sbase;
            const int nchunk = (SEG_CHUNK + 255) / 256;
            for (int c = 0; c < nchunk; c++) {
                int gi = s0 + c * 256 + tid;
                int dv = (gi < s1) ? g_deg[gi] : 0;
                int ctot;
                int cex = block_excl_scan(dv, ssc, ctot);
                if (gi < s1) {
                    int rp = run + cex;
                    g_rowptr[gi] = rp;
                    g_cursor[gi] = rp;
                }
                run += ctot;
            }
            if (bid == NCTA - 1 && tid == 0) g_rowptr[N_SEG] = E_AUG;
        }
        grid_bar(3);
        for (int e = gtid; e < E_AUG; e += gstride) {
            int seg, src;
            aug_edge(graph, e, seg, src);
            int pos = atomicAdd(&g_cursor[seg], 1);
            g_csr[pos] = src;
        }
        grid_bar(4);
    }

    // ================= layer items =================
    int warp = tid >> 5, lane = tid & 31;
    int wm = warp & 3, wn = warp >> 2;

    // ldmatrix per-lane row offsets (bytes) within a tile
    u32 rowa = (u32)(wm * 32 + (lane & 15)) * TS + (u32)((lane >> 4) << 3) * 2;
    u32 rowb = (u32)(wn * 64 + ((lane >> 4) << 3) + (lane & 7)) * TS
             + (u32)(((lane >> 3) & 1) << 3) * 2;
    u32 aHb = smb + OFF_AH + rowa, aLb = smb + OFF_AL + rowa;
    u32 bHb = smb + OFF_B + rowb;

    int bsub = tid & 3;            // 32-dim chunk
    int brow_lo = tid >> 2;        // rows 0..63 (pass 0) / +64 (pass 1)

    float acc[2][8][4];
    #pragma unroll
    for (int i = 0; i < 2; i++)
        #pragma unroll
        for (int j = 0; j < 8; j++)
            #pragma unroll
            for (int q = 0; q < 4; q++) acc[i][j][q] = 0.f;

    int i0 = bid * WPC;
    int i1 = min(i0 + WPC, NITEMS);
    if (i0 >= i1) return;

    int cur_t = -1;

    for (int it = i0; it < i1; ++it) {
        int t = it / R_AUG;
        int r = it - t * R_AUG;
        int tb = t * TM;
        int nrows = min(TM, N_NODES - tb);
        int segbase = r * N_NODES + tb;

        if (t != cur_t) {
            if (cur_t >= 0) {
                flush_acc(acc, cur_t, wm, wn, lane);
                #pragma unroll
                for (int i = 0; i < 2; i++)
                    #pragma unroll
                    for (int j = 0; j < 8; j++)
                        #pragma unroll
                        for (int q = 0; q < 4; q++) acc[i][j][q] = 0.f;
            }
            cur_t = t;
        }

        __syncthreads();   // previous GEMM done reading A & B tiles

        // ---- (A) kick B prefetch (buffer free now), overlaps the build ----
        prefetch_B(smb + OFF_B, Bt, r);
        CP_COMMIT();

        // ---- (B) stage rowptr (coalesced) ----
        if (tid <= nrows) sRp[tid] = g_rowptr[segbase + tid];
        __syncthreads();

        // ---- (C) stage edge srcs for the whole item (contiguous span) ----
        int e0 = sRp[0], e1 = sRp[nrows];
        int nE = e1 - e0;
        bool staged = (nE <= ECAP);
        if (staged) {
            for (int j = tid; j < nE; j += 256) sEdge[j] = g_csr[e0 + j];
        }
        __syncthreads();

        // ---- (D) build + convert A tiles: 4 thr/row, 2 row passes ----
        #pragma unroll
        for (int p = 0; p < 2; p++) {
            int row = brow_lo + p * 64;
            float4 a[8];
            #pragma unroll
            for (int q = 0; q < 8; q++) a[q] = make_float4(0.f, 0.f, 0.f, 0.f);
            int deg = 0;
            if (row < nrows) {
                int rs = sRp[row], re = sRp[row + 1];
                deg = re - rs;
                if (staged) {
                    for (int j = rs - e0; j < re - e0; ++j) {
                        int src = sEdge[j];
                        const float4* v = (const float4*)(x + (size_t)src * D + (bsub << 5));
                        #pragma unroll
                        for (int q = 0; q < 8; q++) {
                            float4 w = v[q];
                            a[q].x += w.x; a[q].y += w.y; a[q].z += w.z; a[q].w += w.w;
                        }
                    }
                } else {
                    for (int j = rs; j < re; ++j) {
                        int src = g_csr[j];
                        const float4* v = (const float4*)(x + (size_t)src * D + (bsub << 5));
                        #pragma unroll
                        for (int q = 0; q < 8; q++) {
                            float4 w = v[q];
                            a[q].x += w.x; a[q].y += w.y; a[q].z += w.z; a[q].w += w.w;
                        }
                    }
                }
            }
            float nrm = 1.0f / fmaxf((float)deg, 1.0f);
            char* AH = smem + OFF_AH + row * TS + (bsub << 6);
            char* AL = smem + OFF_AL + row * TS + (bsub << 6);
            #pragma unroll
            for (int q = 0; q < 8; q += 2) {
                // two float4 -> 8 halves -> one u64 per plane pair
                float v0 = a[q].x * nrm,   v1 = a[q].y * nrm;
                float v2 = a[q].z * nrm,   v3 = a[q].w * nrm;
                float v4 = a[q+1].x * nrm, v5 = a[q+1].y * nrm;
                float v6 = a[q+1].z * nrm, v7 = a[q+1].w * nrm;
                u16 h0 = f2h(v0), h1 = f2h(v1), h2 = f2h(v2), h3 = f2h(v3);
                u16 h4 = f2h(v4), h5 = f2h(v5), h6 = f2h(v6), h7 = f2h(v7);
                u64 H0 = (u64)h0 | ((u64)h1 << 16) | ((u64)h2 << 32) | ((u64)h3 << 48);
                u64 H1 = (u64)h4 | ((u64)h5 << 16) | ((u64)h6 << 32) | ((u64)h7 << 48);
                *(u64*)(AH + q * 8)       = H0;
                *(u64*)(AH + q * 8 + 8)   = H1;
                u16 l0 = f2h(v0 - h2f(h0)), l1 = f2h(v1 - h2f(h1));
                u16 l2 = f2h(v2 - h2f(h2)), l3 = f2h(v3 - h2f(h3));
                u16 l4 = f2h(v4 - h2f(h4)), l5 = f2h(v5 - h2f(h5));
                u16 l6 = f2h(v6 - h2f(h6)), l7 = f2h(v7 - h2f(h7));
                u64 L0 = (u64)l0 | ((u64)l1 << 16) | ((u64)l2 << 32) | ((u64)l3 << 48);
                u64 L1 = (u64)l4 | ((u64)l5 << 16) | ((u64)l6 << 32) | ((u64)l7 << 48);
                *(u64*)(AL + q * 8)       = L0;
                *(u64*)(AL + q * 8 + 8)   = L1;
            }
        }

        // ---- (E) wait B, then 128x128x128 GEMM, 2-term fp16 split ----
        CP_WAIT0();
        __syncthreads();

        #pragma unroll
        for (int ks = 0; ks < 8; ks++) {
            u32 k2 = (u32)ks * 32;                  // k0 * 2 bytes
            u32 aH0[4], aH1[4], aL0[4], aL1[4];
            LDSM4(aH0, aHb + k2);
            LDSM4(aH1, aHb + 16 * TS + k2);
            LDSM4(aL0, aLb + k2);
            LDSM4(aL1, aLb + 16 * TS + k2);
            #pragma unroll
            for (int nh = 0; nh < 4; nh++) {
                u32 bH[4];
                LDSM4(bH, bHb + (u32)nh * 16 * TS + k2);
                int n0 = nh * 2, n1 = nh * 2 + 1;
                MMA16816(acc[0][n0], aH0, bH[0], bH[1]);
                MMA16816(acc[0][n0], aL0, bH[0], bH[1]);
                MMA16816(acc[1][n0], aH1, bH[0], bH[1]);
                MMA16816(acc[1][n0], aL1, bH[0], bH[1]);
                MMA16816(acc[0][n1], aH0, bH[2], bH[3]);
                MMA16816(acc[0][n1], aL0, bH[2], bH[3]);
                MMA16816(acc[1][n1], aH1, bH[2], bH[3]);
                MMA16816(acc[1][n1], aL1, bH[2], bH[3]);
            }
        }
    }

    if (cur_t >= 0) flush_acc(acc, cur_t, wm, wn, lane);
}

// ---------------- reduce slabs + bias (+relu) ----------------
__global__ void reduce_kernel(const float* __restrict__ bias,
                              float* __restrict__ out, int do_relu) {
    int i = blockIdx.x * blockDim.x + threadIdx.x;
    const int n4 = N_NODES * D / 4;
    if (i >= n4) return;
    const float4* p4 = (const float4*)g_partial;
    float4 s = p4[i];
    #pragma unroll
    for (int k = 1; k < NSLAB; k++) {
        float4 t = p4[i + (size_t)k * n4];
        s.x += t.x; s.y += t.y; s.z += t.z; s.w += t.w;
    }
    float4 b = ((const float4*)bias)[i & 31];
    s.x += b.x; s.y += b.y; s.z += b.z; s.w += b.w;
    if (do_relu) {
        s.x = fmaxf(s.x, 0.f); s.y = fmaxf(s.y, 0.f);
        s.z = fmaxf(s.z, 0.f); s.w = fmaxf(s.w, 0.f);
    }
    ((float4*)out)[i] = s;
}

// ---------------- scoring: warp per batch item ----------------
__global__ void score_kernel(const int* __restrict__ batch,
                             const float* __restrict__ xn,
                             const float* __restrict__ rels,
                             float* __restrict__ out) {
    int w = (blockIdx.x * blockDim.x + threadIdx.x) >> 5;
    int lane = threadIdx.x & 31;
    if (w >= N_BATCH) return;
    int bs = batch[w*3+0], bp = batch[w*3+1], bo = batch[w*3+2];
    float4 a = ((const float4*)(xn + (size_t)bs * D))[lane];
    float4 r = ((const float4*)(rels + (size_t)bp * D))[lane];
    float4 c = ((const float4*)(xn + (size_t)bo * D))[lane];
    float s = a.x*r.x*c.x + a.y*r.y*c.y + a.z*r.z*c.z + a.w*r.w*c.w;
    #pragma unroll
    for (int o = 16; o; o >>= 1) s += __shfl_xor_sync(0xffffffffu, s, o);
    if (lane == 0) out[w] = s;
}

// ---------------- launch ----------------
extern "C" void kernel_launch(void* const* d_in, const int* in_sizes, int n_in,
                              void* d_out, int out_size) {
    const int*   graph = (const int*)d_in[0];
    const int*   batch = (const int*)d_in[1];
    const float* x0    = (const float*)d_in[2];
    const float* W1    = (const float*)d_in[3];
    const float* b1    = (const float*)d_in[4];
    const float* W2    = (const float*)d_in[5];
    const float* b2    = (const float*)d_in[6];
    const float* rels  = (const float*)d_in[7];
    float* out = (float*)d_out;

    void *p_h1 = nullptr, *p_h2 = nullptr, *p_bt1 = nullptr, *p_bt2 = nullptr;
    cudaGetSymbolAddress(&p_h1, g_h1);
    cudaGetSymbolAddress(&p_h2, g_h2);
    cudaGetSymbolAddress(&p_bt1, g_Bt1);
    cudaGetSymbolAddress(&p_bt2, g_Bt2);
    float* h1 = (float*)p_h1;
    float* h2 = (float*)p_h2;
    u16* bt1 = (u16*)p_bt1;
    u16* bt2 = (u16*)p_bt2;

    cudaFuncSetAttribute(layer_mega_kernel,
                         cudaFuncAttributeMaxDynamicSharedMemorySize, SMEM_TOT);

    const int zp_grid = (NSLAB * N_NODES * D / 4 + 255) / 256;
    const int rd_grid = (N_NODES * D / 4 + 255) / 256;

    // launches 1-3: W conversions + partial zero (layer kernel lands in slot 4)
    convert_w_kernel<<<R_AUG, 256>>>(W1, bt1);
    convert_w_kernel<<<R_AUG, 256>>>(W2, bt2);
    zero_partial_kernel<<<zp_grid, 256>>>();

    // layer 1 (builds CSR internally via grid barriers; 296 CTAs = 2/SM)
    layer_mega_kernel<<<NCTA, 256, SMEM_TOT>>>(x0, graph, bt1, 1);
    reduce_kernel<<<rd_grid, 256>>>(b1, h1, 1);

    // layer 2
    zero_partial_kernel<<<zp_grid, 256>>>();
    layer_mega_kernel<<<NCTA, 256, SMEM_TOT>>>(h1, graph, bt2, 0);
    reduce_kernel<<<rd_grid, 256>>>(b2, h2, 0);

    // scoring
    score_kernel<<<(N_BATCH * 32) / 256, 256>>>(batch, h2, rels, out);
}

// round 17
// speedup vs baseline: 1.3781x; 1.0084x over previous
#include <cuda_runtime.h>
#include <cuda_fp16.h>

// ---------------- problem constants ----------------
#define N_NODES 10000
#define N_RELS  50
#define R_AUG   101                    // 2*N_RELS + 1
#define D       128
#define N_EDGES 320000
#define E_AUG   (2*N_EDGES + N_NODES)  // 650000
#define N_SEG   (R_AUG * N_NODES)      // 1010000
#define N_BATCH 65536

// persistent layer config: 2 CTAs/SM, M-tile 128
#define TM      128
#define NTILES  ((N_NODES + TM - 1) / TM)          // 79
#define NITEMS  (NTILES * R_AUG)                   // 7979
#define NCTA    296
#define WPC     ((NITEMS + NCTA - 1) / NCTA)       // 27
#define NSLAB   5
#define SEG_CHUNK ((N_SEG + NCTA - 1) / NCTA)      // 3413

// fp16 tile row stride: 128 + 8 pad = 136 halves = 272 bytes
#define TS      272
#define APLANE  (128 * TS)                          // 34816
#define BPLANE  (128 * TS)                          // 34816

// staged-metadata capacities
#define ECAP    512                                 // edge srcs per buffer (ints)
#define RPB     544                                 // bytes per rowptr slot (129 ints + pad)

// smem layout (bytes)
#define OFF_AH   0                                  // A hi [128][136]
#define OFF_AL   APLANE                             // A lo
#define OFF_B    (2*APLANE)                         // B fp16 [128][136]
#define OFF_EDGE (2*APLANE + BPLANE)                // 2 x ECAP ints
#define OFF_RP   (OFF_EDGE + 2*ECAP*4)              // 3 x RPB
#define SMEM_TOT (OFF_RP + 3*RPB)                   // 110,176 B -> 2/SM

typedef unsigned long long u64;
typedef unsigned int u32;
typedef unsigned short u16;

// ---------------- static device scratch ----------------
__device__ int   g_deg[N_SEG];
__device__ int   g_rowptr[N_SEG + 256];                // padded: 528B tail reads safe
__device__ int   g_cursor[N_SEG];
__device__ int   g_ctasum[NCTA];
__device__ int   g_csr[E_AUG];                         // src only
__device__ u16   g_Bt1[(size_t)R_AUG * 16384];         // layer1 W fp16, row=n col=k
__device__ u16   g_Bt2[(size_t)R_AUG * 16384];         // layer2 W
__device__ float g_h1[N_NODES * D];
__device__ float g_h2[N_NODES * D];
__device__ float g_partial[(size_t)NSLAB * N_NODES * D];
__device__ unsigned g_bcnt[8];                         // grid barrier counters (self-reset)
__device__ unsigned g_brel[8];                         // grid barrier release epochs (monotonic)

// ---------------- small helpers ----------------
__device__ __forceinline__ u32 smem_u32(const void* p) {
    u32 a;
    asm("{ .reg .u64 t; cvta.to.shared.u64 t, %1; cvt.u32.u64 %0, t; }" : "=r"(a) : "l"(p));
    return a;
}
__device__ __forceinline__ u16 f2h(float v) {
    u16 r; asm("cvt.rn.f16.f32 %0, %1;" : "=h"(r) : "f"(v)); return r;
}
__device__ __forceinline__ float h2f(u16 v) {
    float r; asm("cvt.f32.f16 %0, %1;" : "=f"(r) : "h"(v)); return r;
}

#define LDSM4(r, addr)                                                          \
    asm volatile("ldmatrix.sync.aligned.m8n8.x4.shared.b16 {%0,%1,%2,%3}, [%4];"\
        : "=r"((r)[0]), "=r"((r)[1]), "=r"((r)[2]), "=r"((r)[3]) : "r"(addr))

#define MMA16816(c, a, b0_, b1_)                                                \
    asm volatile("mma.sync.aligned.m16n8k16.row.col.f32.f16.f16.f32 "           \
        "{%0,%1,%2,%3}, {%4,%5,%6,%7}, {%8,%9}, {%0,%1,%2,%3};"                 \
        : "+f"((c)[0]), "+f"((c)[1]), "+f"((c)[2]), "+f"((c)[3])                \
        : "r"((a)[0]), "r"((a)[1]), "r"((a)[2]), "r"((a)[3]), "r"(b0_), "r"(b1_))

#define CP_ASYNC16(dst, src)                                                    \
    asm volatile("cp.async.cg.shared.global [%0], [%1], 16;" :: "r"(dst), "l"(src))
#define CP_ASYNC4(dst, src)                                                     \
    asm volatile("cp.async.ca.shared.global [%0], [%1], 4;" :: "r"(dst), "l"(src))
#define CP_COMMIT() asm volatile("cp.async.commit_group;" ::: "memory")
#define CP_WAIT0()  asm volatile("cp.async.wait_group 0;" ::: "memory")

// ---- replay-safe software grid barrier (all NCTA CTAs co-resident: 2/SM) ----
__device__ __forceinline__ void grid_bar(int slot) {
    __threadfence();
    __syncthreads();
    if (threadIdx.x == 0) {
        volatile unsigned* rel = (volatile unsigned*)&g_brel[slot];
        unsigned e0 = *rel;
        unsigned t = atomicAdd(&g_bcnt[slot], 1u);
        if (t == NCTA - 1) {
            g_bcnt[slot] = 0;
            __threadfence();
            atomicAdd(&g_brel[slot], 1u);
        } else {
            while (*rel == e0) { }
        }
        __threadfence();
    }
    __syncthreads();
}

// ---- block exclusive scan over 256 ints; returns exclusive, sets total ----
__device__ __forceinline__ int block_excl_scan(int v, int* ssc, int& total) {
    int lane = threadIdx.x & 31, w = threadIdx.x >> 5;
    int x = v;
    #pragma unroll
    for (int o = 1; o < 32; o <<= 1) {
        int y = __shfl_up_sync(0xffffffffu, x, o);
        if (lane >= o) x += y;
    }
    if (lane == 31) ssc[w] = x;
    __syncthreads();
    if (w == 0) {
        int tval = (lane < 8) ? ssc[lane] : 0;
        #pragma unroll
        for (int o = 1; o < 8; o <<= 1) {
            int y = __shfl_up_sync(0xffffffffu, tval, o);
            if (lane >= o) tval += y;
        }
        if (lane < 8) ssc[lane] = tval;    // inclusive warp totals
    }
    __syncthreads();
    int wbase = (w > 0) ? ssc[w - 1] : 0;
    total = ssc[7];
    __syncthreads();
    return wbase + x - v;
}

__device__ __forceinline__ void aug_edge(const int* __restrict__ g, int e,
                                         int& seg, int& src) {
    if (e < N_EDGES) {
        int s = g[e*3+0], p = g[e*3+1], o = g[e*3+2];
        seg = p * N_NODES + o;  src = s;
    } else if (e < 2*N_EDGES) {
        int e2 = e - N_EDGES;
        int s = g[e2*3+0], p = g[e2*3+1], o = g[e2*3+2];
        seg = (p + N_RELS) * N_NODES + s;  src = o;
    } else {
        int i = e - 2*N_EDGES;
        seg = 2*N_RELS*N_NODES + i;  src = i;
    }
}

// ---------------- W -> fp16 B^T plane (row=n, col=k) ----------------
__global__ void convert_w_kernel(const float* __restrict__ W, u16* __restrict__ Bt) {
    int r = blockIdx.x;
    const float* Wr = W + (size_t)r * (D * D);
    u16* B = Bt + (size_t)r * 16384;
    for (int idx = threadIdx.x; idx < D * D; idx += blockDim.x) {
        int k = idx >> 7, n = idx & 127;
        B[n * D + k] = f2h(Wr[k * D + n]);
    }
}

__global__ void zero_partial_kernel() {
    int i = blockIdx.x * blockDim.x + threadIdx.x;
    const int n4 = NSLAB * N_NODES * D / 4;
    if (i < n4) ((float4*)g_partial)[i] = make_float4(0.f, 0.f, 0.f, 0.f);
}

// ---------------- flush register accumulators to a partial slab ----------------
// warp tile 32x64: wm = warp&3 (m), wn = warp>>2 (n)
__device__ __forceinline__ void flush_acc(float acc[2][8][4], int cur_t,
                                          int wm, int wn, int lane) {
    int slab_i = blockIdx.x - (cur_t * R_AUG) / WPC;
    float* slab = g_partial + (size_t)slab_i * (N_NODES * D);
    int r0 = cur_t * TM + wm * 32 + (lane >> 2);
    int cb = wn * 64 + (lane & 3) * 2;
    #pragma unroll
    for (int mf = 0; mf < 2; mf++) {
        int rowA = r0 + mf * 16;
        int rowB = rowA + 8;
        #pragma unroll
        for (int nf = 0; nf < 8; nf++) {
            int col = cb + nf * 8;
            if (rowA < N_NODES)
                *(float2*)(slab + (size_t)rowA * D + col) =
                    make_float2(acc[mf][nf][0], acc[mf][nf][1]);
            if (rowB < N_NODES)
                *(float2*)(slab + (size_t)rowB * D + col) =
                    make_float2(acc[mf][nf][2], acc[mf][nf][3]);
        }
    }
}

// ---- cp.async prefetch of one relation's fp16 B tile (single plane) ----
__device__ __forceinline__ void prefetch_B(u32 smbuf, const u16* __restrict__ Bt, int r) {
    const char* src_base = (const char*)(Bt + (size_t)r * 16384);
    int tid = threadIdx.x;
    #pragma unroll
    for (int q = 0; q < 8; q++) {
        int idx = tid + q * 256;           // 0..2047 16B chunks
        int row = idx >> 4, c16 = idx & 15;
        u32 dst = smbuf + row * TS + c16 * 16;
        const char* src = src_base + row * 256 + c16 * 16;
        CP_ASYNC16(dst, src);
    }
}

// ---- cp.async stage of a rowptr window (129 ints; segbase 16B-aligned) ----
__device__ __forceinline__ void stage_rp(u32 rpb, int segbase, int tid) {
    if (tid < 33)
        CP_ASYNC16(rpb + tid * 16, (const char*)(g_rowptr + segbase) + tid * 16);
}

// ---- cp.async stage of edge srcs (4-byte, unaligned-ok) ----
__device__ __forceinline__ void stage_edges(u32 eb, int e0, int nE, int tid) {
    for (int j = tid; j < nE; j += 256)
        CP_ASYNC4(eb + j * 4, (const char*)(g_csr + e0 + j));
}

// ---------------- persistent mega kernel: (optional CSR build) + layer ----------------
extern "C" __global__ void __launch_bounds__(256, 2)
layer_mega_kernel(const float* __restrict__ x, const int* __restrict__ graph,
                  const u16* __restrict__ Bt, int build_csr) {
    extern __shared__ char smem[];
    __shared__ int ssc[16];
    __shared__ int sbase;
    u32 smb = smem_u32(smem);

    int tid  = threadIdx.x;
    int bid  = blockIdx.x;
    int gtid = bid * 256 + tid;
    const int gstride = NCTA * 256;

    // ================= CSR build (layer-1 instance only) =================
    if (build_csr) {
        for (int i = gtid; i < N_SEG; i += gstride) g_deg[i] = 0;
        grid_bar(0);
        for (int e = gtid; e < E_AUG; e += gstride) {
            int seg, src;
            aug_edge(graph, e, seg, src);
            atomicAdd(&g_deg[seg], 1);
        }
        grid_bar(1);
        int s0 = bid * SEG_CHUNK;
        int s1 = min(s0 + SEG_CHUNK, N_SEG);
        {
            int lsum = 0;
            for (int i = s0 + tid; i < s1; i += 256) lsum += g_deg[i];
            #pragma unroll
            for (int o = 16; o; o >>= 1) lsum += __shfl_xor_sync(0xffffffffu, lsum, o);
            if ((tid & 31) == 0) ssc[tid >> 5] = lsum;
            __syncthreads();
            if (tid < 8) {
                int v = ssc[tid];
                #pragma unroll
                for (int o = 4; o; o >>= 1) v += __shfl_xor_sync(0xffu, v, o);
                if (tid == 0) g_ctasum[bid] = v;
            }
            __syncthreads();
        }
        grid_bar(2);
        {
            int va = 0, vp = 0;
            if (tid < NCTA / 2) {
                va = g_ctasum[2 * tid];
                vp = va + g_ctasum[2 * tid + 1];
            }
            int tot;
            int ex = block_excl_scan(vp, ssc, tot);
            if (2 * tid == bid) sbase = ex;
            if (2 * tid + 1 == bid) sbase = ex + va;
            __syncthreads();
            int run = sbase;
            const int nchunk = (SEG_CHUNK + 255) / 256;
            for (int c = 0; c < nchunk; c++) {
                int gi = s0 + c * 256 + tid;
                int dv = (gi < s1) ? g_deg[gi] : 0;
                int ctot;
                int cex = block_excl_scan(dv, ssc, ctot);
                if (gi < s1) {
                    int rp = run + cex;
                    g_rowptr[gi] = rp;
                    g_cursor[gi] = rp;
                }
                run += ctot;
            }
            if (bid == NCTA - 1 && tid == 0) g_rowptr[N_SEG] = E_AUG;
        }
        grid_bar(3);
        for (int e = gtid; e < E_AUG; e += gstride) {
            int seg, src;
            aug_edge(graph, e, seg, src);
            int pos = atomicAdd(&g_cursor[seg], 1);
            g_csr[pos] = src;
        }
        grid_bar(4);
    }

    // ================= layer items =================
    int warp = tid >> 5, lane = tid & 31;
    int wm = warp & 3, wn = warp >> 2;

    // ldmatrix per-lane row offsets (bytes) within a tile
    u32 rowa = (u32)(wm * 32 + (lane & 15)) * TS + (u32)((lane >> 4) << 3) * 2;
    u32 rowb = (u32)(wn * 64 + ((lane >> 4) << 3) + (lane & 7)) * TS
             + (u32)(((lane >> 3) & 1) << 3) * 2;
    u32 aHb = smb + OFF_AH + rowa, aLb = smb + OFF_AL + rowa;
    u32 bHb = smb + OFF_B + rowb;

    int bsub = tid & 3;            // 32-dim chunk
    int brow_lo = tid >> 2;        // rows 0..63 (pass 0) / +64 (pass 1)

    float acc[2][8][4];
    #pragma unroll
    for (int i = 0; i < 2; i++)
        #pragma unroll
        for (int j = 0; j < 8; j++)
            #pragma unroll
            for (int q = 0; q < 4; q++) acc[i][j][q] = 0.f;

    int i0 = bid * WPC;
    int i1 = min(i0 + WPC, NITEMS);
    if (i0 >= i1) return;

    int cur_t = -1;

    // ---- prologue: stage rp[i0], rp[i0+1], edges[i0] ----
    {
        int t0 = i0 / R_AUG, r0 = i0 - t0 * R_AUG;
        stage_rp(smb + OFF_RP + (i0 % 3) * RPB, r0 * N_NODES + t0 * TM, tid);
        if (i0 + 1 < i1) {
            int t1 = (i0 + 1) / R_AUG, rr = (i0 + 1) - t1 * R_AUG;
            stage_rp(smb + OFF_RP + ((i0 + 1) % 3) * RPB, rr * N_NODES + t1 * TM, tid);
        }
        CP_COMMIT(); CP_WAIT0(); __syncthreads();
        int nr0 = min(TM, N_NODES - t0 * TM);
        int* rp0 = (int*)(smem + OFF_RP + (i0 % 3) * RPB);
        int e0 = rp0[0], e1 = rp0[nr0];
        if (e1 - e0 <= ECAP)
            stage_edges(smb + OFF_EDGE + (i0 & 1) * ECAP * 4, e0, e1 - e0, tid);
        CP_COMMIT(); CP_WAIT0(); __syncthreads();
    }

    for (int it = i0; it < i1; ++it) {
        int t = it / R_AUG;
        int r = it - t * R_AUG;
        int tb = t * TM;
        int nrows = min(TM, N_NODES - tb);

        if (t != cur_t) {
            if (cur_t >= 0) {
                flush_acc(acc, cur_t, wm, wn, lane);
                #pragma unroll
                for (int i = 0; i < 2; i++)
                    #pragma unroll
                    for (int j = 0; j < 8; j++)
                        #pragma unroll
                        for (int q = 0; q < 4; q++) acc[i][j][q] = 0.f;
            }
            cur_t = t;
        }

        // (loop-top state: A & B free, rp[it], rp[it+1], edges[it] staged & visible)
        int* rpI = (int*)(smem + OFF_RP + (it % 3) * RPB);

        // ---- (A) fire this window's async group: B[it], rp[it+2], edges[it+1] ----
        prefetch_B(smb + OFF_B, Bt, r);
        if (it + 2 < i1) {
            int t2 = (it + 2) / R_AUG, r2 = (it + 2) - t2 * R_AUG;
            stage_rp(smb + OFF_RP + ((it + 2) % 3) * RPB, r2 * N_NODES + t2 * TM, tid);
        }
        if (it + 1 < i1) {
            int t1 = (it + 1) / R_AUG;
            int nr1 = min(TM, N_NODES - t1 * TM);
            int* rpN = (int*)(smem + OFF_RP + ((it + 1) % 3) * RPB);
            int e0n = rpN[0], e1n = rpN[nr1];
            if (e1n - e0n <= ECAP)
                stage_edges(smb + OFF_EDGE + ((it + 1) & 1) * ECAP * 4, e0n, e1n - e0n, tid);
        }
        CP_COMMIT();

        // ---- (B) build + convert A tiles from staged metadata ----
        int e0 = rpI[0];
        bool staged = (rpI[nrows] - e0 <= ECAP);
        const int* sEd = (const int*)(smem + OFF_EDGE + (it & 1) * ECAP * 4);
        #pragma unroll
        for (int p = 0; p < 2; p++) {
            int row = brow_lo + p * 64;
            float4 a[8];
            #pragma unroll
            for (int q = 0; q < 8; q++) a[q] = make_float4(0.f, 0.f, 0.f, 0.f);
            int deg = 0;
            if (row < nrows) {
                int rs = rpI[row], re = rpI[row + 1];
                deg = re - rs;
                if (staged) {
                    for (int j = rs - e0; j < re - e0; ++j) {
                        int src = sEd[j];
                        const float4* v = (const float4*)(x + (size_t)src * D + (bsub << 5));
                        #pragma unroll
                        for (int q = 0; q < 8; q++) {
                            float4 w = v[q];
                            a[q].x += w.x; a[q].y += w.y; a[q].z += w.z; a[q].w += w.w;
                        }
                    }
                } else {
                    for (int j = rs; j < re; ++j) {
                        int src = g_csr[j];
                        const float4* v = (const float4*)(x + (size_t)src * D + (bsub << 5));
                        #pragma unroll
                        for (int q = 0; q < 8; q++) {
                            float4 w = v[q];
                            a[q].x += w.x; a[q].y += w.y; a[q].z += w.z; a[q].w += w.w;
                        }
                    }
                }
            }
            float nrm = 1.0f / fmaxf((float)deg, 1.0f);
            char* AH = smem + OFF_AH + row * TS + (bsub << 6);
            char* AL = smem + OFF_AL + row * TS + (bsub << 6);
            #pragma unroll
            for (int q = 0; q < 8; q += 2) {
                float v0 = a[q].x * nrm,   v1 = a[q].y * nrm;
                float v2 = a[q].z * nrm,   v3 = a[q].w * nrm;
                float v4 = a[q+1].x * nrm, v5 = a[q+1].y * nrm;
                float v6 = a[q+1].z * nrm, v7 = a[q+1].w * nrm;
                u16 h0 = f2h(v0), h1 = f2h(v1), h2 = f2h(v2), h3 = f2h(v3);
                u16 h4 = f2h(v4), h5 = f2h(v5), h6 = f2h(v6), h7 = f2h(v7);
                u64 H0 = (u64)h0 | ((u64)h1 << 16) | ((u64)h2 << 32) | ((u64)h3 << 48);
                u64 H1 = (u64)h4 | ((u64)h5 << 16) | ((u64)h6 << 32) | ((u64)h7 << 48);
                *(u64*)(AH + q * 8)     = H0;
                *(u64*)(AH + q * 8 + 8) = H1;
                u16 l0 = f2h(v0 - h2f(h0)), l1 = f2h(v1 - h2f(h1));
                u16 l2 = f2h(v2 - h2f(h2)), l3 = f2h(v3 - h2f(h3));
                u16 l4 = f2h(v4 - h2f(h4)), l5 = f2h(v5 - h2f(h5));
                u16 l6 = f2h(v6 - h2f(h6)), l7 = f2h(v7 - h2f(h7));
                u64 L0 = (u64)l0 | ((u64)l1 << 16) | ((u64)l2 << 32) | ((u64)l3 << 48);
                u64 L1 = (u64)l4 | ((u64)l5 << 16) | ((u64)l6 << 32) | ((u64)l7 << 48);
                *(u64*)(AL + q * 8)     = L0;
                *(u64*)(AL + q * 8 + 8) = L1;
            }
        }

        // ---- (C) drain async group (B[it] + next metadata), publish A ----
        CP_WAIT0();
        __syncthreads();

        // ---- (D) 128x128x128 GEMM, 2-term fp16 split ----
        #pragma unroll
        for (int ks = 0; ks < 8; ks++) {
            u32 k2 = (u32)ks * 32;                  // k0 * 2 bytes
            u32 aH0[4], aH1[4], aL0[4], aL1[4];
            LDSM4(aH0, aHb + k2);
            LDSM4(aH1, aHb + 16 * TS + k2);
            LDSM4(aL0, aLb + k2);
            LDSM4(aL1, aLb + 16 * TS + k2);
            #pragma unroll
            for (int nh = 0; nh < 4; nh++) {
                u32 bH[4];
                LDSM4(bH, bHb + (u32)nh * 16 * TS + k2);
                int n0 = nh * 2, n1 = nh * 2 + 1;
                MMA16816(acc[0][n0], aH0, bH[0], bH[1]);
                MMA16816(acc[0][n0], aL0, bH[0], bH[1]);
                MMA16816(acc[1][n0], aH1, bH[0], bH[1]);
                MMA16816(acc[1][n0], aL1, bH[0], bH[1]);
                MMA16816(acc[0][n1], aH0, bH[2], bH[3]);
                MMA16816(acc[0][n1], aL0, bH[2], bH[3]);
                MMA16816(acc[1][n1], aH1, bH[2], bH[3]);
                MMA16816(acc[1][n1], aL1, bH[2], bH[3]);
            }
        }
        __syncthreads();   // GEMM done: A, B, and staged buffers reusable next window
    }

    if (cur_t >= 0) flush_acc(acc, cur_t, wm, wn, lane);
}

// ---------------- reduce slabs + bias (+relu) ----------------
__global__ void reduce_kernel(const float* __restrict__ bias,
                              float* __restrict__ out, int do_relu) {
    int i = blockIdx.x * blockDim.x + threadIdx.x;
    const int n4 = N_NODES * D / 4;
    if (i >= n4) return;
    const float4* p4 = (const float4*)g_partial;
    float4 s = p4[i];
    #pragma unroll
    for (int k = 1; k < NSLAB; k++) {
        float4 t = p4[i + (size_t)k * n4];
        s.x += t.x; s.y += t.y; s.z += t.z; s.w += t.w;
    }
    float4 b = ((const float4*)bias)[i & 31];
    s.x += b.x; s.y += b.y; s.z += b.z; s.w += b.w;
    if (do_relu) {
        s.x = fmaxf(s.x, 0.f); s.y = fmaxf(s.y, 0.f);
        s.z = fmaxf(s.z, 0.f); s.w = fmaxf(s.w, 0.f);
    }
    ((float4*)out)[i] = s;
}

// ---------------- scoring: warp per batch item ----------------
__global__ void score_kernel(const int* __restrict__ batch,
                             const float* __restrict__ xn,
                             const float* __restrict__ rels,
                             float* __restrict__ out) {
    int w = (blockIdx.x * blockDim.x + threadIdx.x) >> 5;
    int lane = threadIdx.x & 31;
    if (w >= N_BATCH) return;
    int bs = batch[w*3+0], bp = batch[w*3+1], bo = batch[w*3+2];
    float4 a = ((const float4*)(xn + (size_t)bs * D))[lane];
    float4 r = ((const float4*)(rels + (size_t)bp * D))[lane];
    float4 c = ((const float4*)(xn + (size_t)bo * D))[lane];
    float s = a.x*r.x*c.x + a.y*r.y*c.y + a.z*r.z*c.z + a.w*r.w*c.w;
    #pragma unroll
    for (int o = 16; o; o >>= 1) s += __shfl_xor_sync(0xffffffffu, s, o);
    if (lane == 0) out[w] = s;
}

// ---------------- launch ----------------
extern "C" void kernel_launch(void* const* d_in, const int* in_sizes, int n_in,
                              void* d_out, int out_size) {
    const int*   graph = (const int*)d_in[0];
    const int*   batch = (const int*)d_in[1];
    const float* x0    = (const float*)d_in[2];
    const float* W1    = (const float*)d_in[3];
    const float* b1    = (const float*)d_in[4];
    const float* W2    = (const float*)d_in[5];
    const float* b2    = (const float*)d_in[6];
    const float* rels  = (const float*)d_in[7];
    float* out = (float*)d_out;

    void *p_h1 = nullptr, *p_h2 = nullptr, *p_bt1 = nullptr, *p_bt2 = nullptr;
    cudaGetSymbolAddress(&p_h1, g_h1);
    cudaGetSymbolAddress(&p_h2, g_h2);
    cudaGetSymbolAddress(&p_bt1, g_Bt1);
    cudaGetSymbolAddress(&p_bt2, g_Bt2);
    float* h1 = (float*)p_h1;
    float* h2 = (float*)p_h2;
    u16* bt1 = (u16*)p_bt1;
    u16* bt2 = (u16*)p_bt2;

    cudaFuncSetAttribute(layer_mega_kernel,
                         cudaFuncAttributeMaxDynamicSharedMemorySize, SMEM_TOT);

    const int zp_grid = (NSLAB * N_NODES * D / 4 + 255) / 256;
    const int rd_grid = (N_NODES * D / 4 + 255) / 256;

    // launches 1-3: W conversions + partial zero (layer kernel lands in slot 4)
    convert_w_kernel<<<R_AUG, 256>>>(W1, bt1);
    convert_w_kernel<<<R_AUG, 256>>>(W2, bt2);
    zero_partial_kernel<<<zp_grid, 256>>>();

    // layer 1 (builds CSR internally via grid barriers; 296 CTAs = 2/SM)
    layer_mega_kernel<<<NCTA, 256, SMEM_TOT>>>(x0, graph, bt1, 1);
    reduce_kernel<<<rd_grid, 256>>>(b1, h1, 1);

    // layer 2
    zero_partial_kernel<<<zp_grid, 256>>>();
    layer_mega_kernel<<<NCTA, 256, SMEM_TOT>>>(h1, graph, bt2, 0);
    reduce_kernel<<<rd_grid, 256>>>(b2, h2, 0);

    // scoring
    score_kernel<<<(N_BATCH * 32) / 256, 256>>>(batch, h2, rels, out);
}